// round 2
// baseline (speedup 1.0000x reference)
#include <cuda_runtime.h>
#include <math.h>

// Problem constants (fixed by the dataset)
#define Dq 256
#define Hq 256
#define Kq 11
#define MT 16          // rows per CTA
#define NTHREADS 256   // one thread per output column

// Dynamic smem layout (in floats):
//   Xs : [256][16]            4096   (input x tile, transposed [d][m])
//   Hs : [256][16]            4096   (hidden buffer / phase-2 scratch)
//   TXs: [256][16] or z[16][256] 4096
//   ZT : [11][16][256]       45056   (zt vectors, [k][m][j])
// total = 57344 floats = 229376 bytes (< 232448 max dynamic)
#define XS_OFF 0
#define HS_OFF 4096
#define TX_OFF 8192
#define ZT_OFF 12288
#define SMEM_FLOATS 57344

__device__ __forceinline__ float gelu_exact(float v) {
    return 0.5f * v * (1.0f + erff(v * 0.70710678118654752f));
}

// O[j, m] = act( sum_d In[d][m] * W[d*256 + j] + bias[j] )
// In layout: In[d*MT + m]. Output written at Out[m*om + j*oj].
__device__ __forceinline__ void gemm_step(
    const float* __restrict__ W, const float* __restrict__ bias,
    const float* __restrict__ In, float* __restrict__ Out,
    int j, bool do_gelu, int om, int oj)
{
    float acc[MT];
    {
        float b = bias[j];
#pragma unroll
        for (int m = 0; m < MT; ++m) acc[m] = b;
    }

    // double-buffered weight column loads (8-deep MLP against L2 latency)
    float w[8];
#pragma unroll
    for (int u = 0; u < 8; ++u) w[u] = W[u * 256 + j];

    for (int d = 0; d < 256; d += 8) {
        float wn[8];
        if (d + 8 < 256) {
#pragma unroll
            for (int u = 0; u < 8; ++u) wn[u] = W[(d + 8 + u) * 256 + j];
        }
#pragma unroll
        for (int u = 0; u < 8; ++u) {
            const float4* xr = reinterpret_cast<const float4*>(In + (d + u) * MT);
            float wu = w[u];
#pragma unroll
            for (int q = 0; q < 4; ++q) {
                float4 xv = xr[q];   // broadcast LDS.128 (all lanes same addr)
                acc[q * 4 + 0] = fmaf(xv.x, wu, acc[q * 4 + 0]);
                acc[q * 4 + 1] = fmaf(xv.y, wu, acc[q * 4 + 1]);
                acc[q * 4 + 2] = fmaf(xv.z, wu, acc[q * 4 + 2]);
                acc[q * 4 + 3] = fmaf(xv.w, wu, acc[q * 4 + 3]);
            }
        }
#pragma unroll
        for (int u = 0; u < 8; ++u) w[u] = wn[u];
    }

#pragma unroll
    for (int m = 0; m < MT; ++m) {
        float v = acc[m];
        if (do_gelu) v = gelu_exact(v);
        Out[m * om + j * oj] = v;
    }
}

// dot over 256 elements, conflict-free (lane-strided), result valid on lane 0
__device__ __forceinline__ float warp_dot256(const float* __restrict__ a,
                                             const float* __restrict__ b, int lane)
{
    float s = 0.f;
#pragma unroll
    for (int u = 0; u < 8; ++u) {
        int j = u * 32 + lane;
        s = fmaf(a[j], b[j], s);
    }
#pragma unroll
    for (int off = 16; off; off >>= 1)
        s += __shfl_down_sync(0xffffffffu, s, off);
    return s;
}

extern __shared__ float smem[];

__global__ void __launch_bounds__(NTHREADS, 1)
neutralad_fused_kernel(
    const float* __restrict__ x,
    const float* __restrict__ Tw1, const float* __restrict__ Tb1,
    const float* __restrict__ Tw2, const float* __restrict__ Tb2,
    const float* __restrict__ Ew1, const float* __restrict__ Eb1,
    const float* __restrict__ Ew2, const float* __restrict__ Eb2,
    float* __restrict__ out)
{
    const int j = threadIdx.x;           // output column / d index
    const long long b0 = (long long)blockIdx.x * MT;

    float* Xs  = smem + XS_OFF;
    float* Hs  = smem + HS_OFF;
    float* TXs = smem + TX_OFF;
    float* ZTs = smem + ZT_OFF;

    // ---- load X tile, transposed: Xs[d][m] ----
#pragma unroll
    for (int m = 0; m < MT; ++m)
        Xs[j * MT + m] = x[(b0 + m) * Dq + j];
    __syncthreads();

    // ---- K transforms + their encoders ----
    for (int k = 0; k < Kq; ++k) {
        // h1 = gelu(x @ Tw1_k + Tb1_k)
        gemm_step(Tw1 + (size_t)k * Dq * Hq, Tb1 + k * Hq, Xs, Hs, j, true, 1, MT);
        __syncthreads();
        // tx = h1 @ Tw2_k + Tb2_k
        gemm_step(Tw2 + (size_t)k * Hq * Dq, Tb2 + k * Dq, Hs, TXs, j, false, 1, MT);
        __syncthreads();
        // e1 = gelu(tx @ Ew1 + Eb1)
        gemm_step(Ew1, Eb1, TXs, Hs, j, true, 1, MT);
        __syncthreads();
        // zt_k = e1 @ Ew2 + Eb2  -> ZT[k][m][j] ([m][j] layout, conflict-free writes)
        gemm_step(Ew2, Eb2, Hs, ZTs + (size_t)k * MT * Hq, j, false, Hq, 1);
        __syncthreads();
    }

    // ---- z = enc(x), stored into TXs as [m][j] ----
    gemm_step(Ew1, Eb1, Xs, Hs, j, true, 1, MT);
    __syncthreads();
    gemm_step(Ew2, Eb2, Hs, TXs, j, false, Hq, 1);
    __syncthreads();

    // ---- phase 2: per-row similarity scoring ----
    // Hs is free now -> scratch [16][256] per-row dot storage:
    //   [l*11+k] pair dots (symmetric), [132+k] z·zt_k, [144+k] ||zt_k||, [160] ||z||
    const int warp = threadIdx.x >> 5;
    const int lane = threadIdx.x & 31;

#pragma unroll
    for (int mi = 0; mi < 2; ++mi) {
        const int m = warp * 2 + mi;
        float* sc = Hs + m * 256;
        const float* zrow = TXs + m * Hq;

        // norms of zt_k
        for (int k = 0; k < Kq; ++k) {
            const float* a = ZTs + ((size_t)k * MT + m) * Hq;
            float s = warp_dot256(a, a, lane);
            if (lane == 0) sc[144 + k] = sqrtf(s);
        }
        // norm of z
        {
            float s = warp_dot256(zrow, zrow, lane);
            if (lane == 0) sc[160] = sqrtf(s);
        }
        // z · zt_k
        for (int k = 0; k < Kq; ++k) {
            const float* a = ZTs + ((size_t)k * MT + m) * Hq;
            float s = warp_dot256(zrow, a, lane);
            if (lane == 0) sc[132 + k] = s;
        }
        // zt_l · zt_k (l < k), stored symmetric
        for (int l = 0; l < Kq; ++l) {
            const float* a = ZTs + ((size_t)l * MT + m) * Hq;
            for (int k = l + 1; k < Kq; ++k) {
                const float* bb = ZTs + ((size_t)k * MT + m) * Hq;
                float s = warp_dot256(a, bb, lane);
                if (lane == 0) { sc[l * 11 + k] = s; sc[k * 11 + l] = s; }
            }
        }
        __syncwarp();

        // score_m = sum_k log1p(neg_k / sim_z_k)
        float term = 0.f;
        if (lane < Kq) {
            const int k = lane;
            const float nz = sc[160];
            const float nk = sc[144 + k];
            const float sim = expf(sc[132 + k] / fmaxf(nz * nk, 1e-8f));
            float neg = 0.f;
#pragma unroll
            for (int l = 0; l < Kq; ++l) {
                if (l == k) continue;
                const float nl = sc[144 + l];
                neg += expf(sc[l * 11 + k] / fmaxf(nl * nk, 1e-8f));
            }
            term = log1pf(neg / sim);
        }
#pragma unroll
        for (int off = 16; off; off >>= 1)
            term += __shfl_down_sync(0xffffffffu, term, off);
        if (lane == 0) out[b0 + m] = term;
    }
}

extern "C" void kernel_launch(void* const* d_in, const int* in_sizes, int n_in,
                              void* d_out, int out_size)
{
    const float* x   = (const float*)d_in[0];
    const float* Tw1 = (const float*)d_in[1];
    const float* Tb1 = (const float*)d_in[2];
    const float* Tw2 = (const float*)d_in[3];
    const float* Tb2 = (const float*)d_in[4];
    const float* Ew1 = (const float*)d_in[5];
    const float* Eb1 = (const float*)d_in[6];
    const float* Ew2 = (const float*)d_in[7];
    const float* Eb2 = (const float*)d_in[8];
    float* out = (float*)d_out;

    const int B = in_sizes[0] / Dq;
    const int grid = B / MT;
    const size_t smem_bytes = SMEM_FLOATS * sizeof(float);

    cudaFuncSetAttribute(neutralad_fused_kernel,
                         cudaFuncAttributeMaxDynamicSharedMemorySize,
                         (int)smem_bytes);

    neutralad_fused_kernel<<<grid, NTHREADS, smem_bytes>>>(
        x, Tw1, Tb1, Tw2, Tb2, Ew1, Eb1, Ew2, Eb2, out);
}

// round 4
// speedup vs baseline: 2.6850x; 2.6850x over previous
#include <cuda_runtime.h>
#include <cuda_bf16.h>
#include <math.h>
#include <stdint.h>

#define Bq 65536

// ---------------- device workspaces (sanctioned __device__ scratch) --------
// 24 matrices, each stored BT[n][k] bf16: hi part (128KB) then lo part (128KB)
__device__ __align__(16) unsigned char g_wb[24u * 262144u];   // 6 MB
__device__ float g_z[12ull * Bq * 256ull];                    // z vectors fp32

// ---------------- SMEM layout (bytes) ----------------
// bias f32[256]                      @ 0      (1024)
// A0_hi [64][264] bf16               @ 1024   (33792)
// A0_lo                              @ 34816
// A1_hi                              @ 68608
// A1_lo                              @ 102400
// B stages: 2 x { hi[32][264], lo }  @ 136192 (2 x 33792)
#define BIAS_OFF 0
#define SM_BYTES 203776
#define BST_OFF 136192
#define BPART 16896          // 32*528
#define ASTRIDE 528          // bytes per activation row (264 bf16)

__constant__ int c_AH[2] = {1024, 68608};
__constant__ int c_AL[2] = {34816, 102400};

// ---------------- helpers ----------------
__device__ __forceinline__ uint32_t smem_u32(const void* p) {
    uint32_t a;
    asm("{ .reg .u64 t; cvta.to.shared.u64 t, %1; cvt.u32.u64 %0, t; }" : "=r"(a) : "l"(p));
    return a;
}

#define LDSM4(r, addr) \
    asm volatile("ldmatrix.sync.aligned.m8n8.x4.shared.b16 {%0,%1,%2,%3}, [%4];" \
        : "=r"((r)[0]), "=r"((r)[1]), "=r"((r)[2]), "=r"((r)[3]) : "r"(addr))

#define MMA(acc, a, bb0, bb1) \
    asm volatile("mma.sync.aligned.m16n8k16.row.col.f32.bf16.bf16.f32 " \
        "{%0,%1,%2,%3},{%4,%5,%6,%7},{%8,%9},{%0,%1,%2,%3};" \
        : "+f"((acc)[0]), "+f"((acc)[1]), "+f"((acc)[2]), "+f"((acc)[3]) \
        : "r"((a)[0]), "r"((a)[1]), "r"((a)[2]), "r"((a)[3]), "r"(bb0), "r"(bb1))

__device__ __forceinline__ void cpa16(uint32_t dst, const void* src) {
    asm volatile("cp.async.cg.shared.global [%0], [%1], 16;" :: "r"(dst), "l"(src));
}
#define CP_COMMIT() asm volatile("cp.async.commit_group;" ::: "memory")
#define CP_WAIT0()  asm volatile("cp.async.wait_group 0;" ::: "memory")

__device__ __forceinline__ uint32_t pack_hi_lo(float a, float b, uint32_t* lo) {
    __nv_bfloat16 ha = __float2bfloat16(a), hb = __float2bfloat16(b);
    float ra = a - __bfloat162float(ha), rb = b - __bfloat162float(hb);
    __nv_bfloat162 hh = __halves2bfloat162(ha, hb);
    __nv_bfloat162 ll = __halves2bfloat162(__float2bfloat16(ra), __float2bfloat16(rb));
    *lo = *(uint32_t*)&ll;
    return *(uint32_t*)&hh;
}

__device__ __forceinline__ float gelu_f(float v) {
    return 0.5f * v * (1.0f + erff(v * 0.70710678118654752f));
}

// ---------------- prep: weights -> BT hi/lo bf16 blobs ----------------
__global__ void prep_kernel(const float* __restrict__ Tw1, const float* __restrict__ Tw2,
                            const float* __restrict__ Ew1, const float* __restrict__ Ew2) {
    int mat = blockIdx.x;
    const float* src = (mat < 11) ? Tw1 + (size_t)mat * 65536
                     : (mat < 22) ? Tw2 + (size_t)(mat - 11) * 65536
                     : (mat == 22) ? Ew1 : Ew2;
    unsigned char* baseH = g_wb + (size_t)mat * 262144u;
    for (int idx = threadIdx.x; idx < 65536; idx += blockDim.x) {
        int k = idx >> 8, n = idx & 255;     // src[k][n], reduction k, output n
        float wv = src[idx];
        __nv_bfloat16 h = __float2bfloat16(wv);
        float r = wv - __bfloat162float(h);
        __nv_bfloat16 l = __float2bfloat16(r);
        size_t off = (size_t)n * 512 + (size_t)k * 2;
        *(unsigned short*)(baseH + off) = *(unsigned short*)&h;
        *(unsigned short*)(baseH + 131072u + off) = *(unsigned short*)&l;
    }
}

// ---------------- main fused MLP kernel ----------------
extern __shared__ unsigned char smem[];

__device__ __forceinline__ void issueB(uint32_t sb, int tid, int mat, int c, int stage) {
    const unsigned char* srcbase = g_wb + (size_t)mat * 262144u;
    uint32_t dstbase = sb + BST_OFF + stage * (2 * BPART);
#pragma unroll
    for (int i = 0; i < 8; ++i) {
        int g = tid + 256 * i;           // 0..2047
        int part = g >> 10;              // hi / lo
        int rem = g & 1023;
        int rw = rem >> 5;               // row within chunk 0..31
        int u = rem & 31;                // 16B unit within 512B row
        uint32_t dst = dstbase + part * BPART + rw * ASTRIDE + u * 16;
        const unsigned char* s = srcbase + (size_t)part * 131072u
                               + (size_t)(c * 32 + rw) * 512 + (size_t)u * 16;
        cpa16(dst, s);
    }
    CP_COMMIT();
}

__device__ __forceinline__ void do_layer(
    uint32_t sb, int tid, int cur, int mat,
    const float* __restrict__ biasPtr, bool do_gelu, bool toA,
    int slot, int b0)
{
    float* bias_s = (float*)(smem + BIAS_OFF);
    bias_s[tid] = biasPtr[tid];

    const int w = tid >> 5, lane = tid & 31;
    const int wm = w >> 1, wn = w & 1;
    const int gid = lane >> 2, tig = lane & 3;

    // ldmatrix lane addresses (constant parts)
    const int rowA = wm * 16 + (lane & 15);
    const int koffA = (lane >> 4) * 16;                      // bytes
    const int rowB = wn * 16 + ((lane >> 4) << 3) + (lane & 7);
    const int koffB = ((lane >> 3) & 1) * 16;

    const uint32_t aHbase = sb + c_AH[cur] + rowA * ASTRIDE + koffA;
    const uint32_t aLbase = sb + c_AL[cur] + rowA * ASTRIDE + koffA;

    issueB(sb, tid, mat, 0, 0);

#pragma unroll 1
    for (int c = 0; c < 8; ++c) {
        CP_WAIT0();
        __syncthreads();
        if (c + 1 < 8) issueB(sb, tid, mat, c + 1, (c + 1) & 1);

        const uint32_t bbase = sb + BST_OFF + (c & 1) * (2 * BPART)
                             + rowB * ASTRIDE + koffB;
        uint32_t aH = aHbase, aL = aLbase;
        uint32_t bH = bbase, bL = bbase + BPART;

        float acc0[4] = {0.f, 0.f, 0.f, 0.f};
        float acc1[4] = {0.f, 0.f, 0.f, 0.f};

#pragma unroll
        for (int ks = 0; ks < 16; ++ks) {
            uint32_t ah[4], al[4], bh[4], bl[4];
            LDSM4(ah, aH); LDSM4(al, aL); LDSM4(bh, bH); LDSM4(bl, bL);
            aH += 32; aL += 32; bH += 32; bL += 32;
            MMA(acc0, ah, bh[0], bh[1]); MMA(acc1, ah, bh[2], bh[3]);
            MMA(acc0, al, bh[0], bh[1]); MMA(acc1, al, bh[2], bh[3]);
            MMA(acc0, ah, bl[0], bl[1]); MMA(acc1, ah, bl[2], bl[3]);
        }

        // epilogue for this 64x32 chunk
        const int r0 = wm * 16 + gid;
#pragma unroll
        for (int t = 0; t < 2; ++t) {
            float* ac = t ? acc1 : acc0;
            const int gcol = c * 32 + wn * 16 + t * 8 + 2 * tig;
            float v00 = ac[0] + bias_s[gcol];
            float v01 = ac[1] + bias_s[gcol + 1];
            float v10 = ac[2] + bias_s[gcol];
            float v11 = ac[3] + bias_s[gcol + 1];
            if (do_gelu) {
                v00 = gelu_f(v00); v01 = gelu_f(v01);
                v10 = gelu_f(v10); v11 = gelu_f(v11);
            }
            if (toA) {
                uint32_t lo0, lo1;
                uint32_t hi0 = pack_hi_lo(v00, v01, &lo0);
                uint32_t hi1 = pack_hi_lo(v10, v11, &lo1);
                unsigned char* dh = smem + c_AH[cur ^ 1];
                unsigned char* dl = smem + c_AL[cur ^ 1];
                *(uint32_t*)(dh + r0 * ASTRIDE + gcol * 2) = hi0;
                *(uint32_t*)(dl + r0 * ASTRIDE + gcol * 2) = lo0;
                *(uint32_t*)(dh + (r0 + 8) * ASTRIDE + gcol * 2) = hi1;
                *(uint32_t*)(dl + (r0 + 8) * ASTRIDE + gcol * 2) = lo1;
            } else {
                float* z0 = g_z + ((size_t)slot * Bq + b0 + r0) * 256 + gcol;
                float* z1 = g_z + ((size_t)slot * Bq + b0 + r0 + 8) * 256 + gcol;
                *(float2*)z0 = make_float2(v00, v01);
                *(float2*)z1 = make_float2(v10, v11);
            }
        }
    }
    __syncthreads();
}

__global__ void __launch_bounds__(256, 1)
mlp_kernel(const float* __restrict__ x,
           const float* __restrict__ Tb1, const float* __restrict__ Tb2,
           const float* __restrict__ Eb1, const float* __restrict__ Eb2)
{
    const uint32_t sb = smem_u32(smem);
    const int tid = threadIdx.x;
    const int b0 = blockIdx.x * 64;

#pragma unroll 1
    for (int br = 0; br < 12; ++br) {
        // load x rows -> A0 (hi/lo split)
        {
            const int row = tid >> 2;
            const int cbase = (tid & 3) * 64;
            const float4* src = (const float4*)(x + (size_t)(b0 + row) * 256 + cbase);
            unsigned char* ah = smem + c_AH[0] + row * ASTRIDE;
            unsigned char* al = smem + c_AL[0] + row * ASTRIDE;
#pragma unroll
            for (int i = 0; i < 16; ++i) {
                float4 v = src[i];
                int col = cbase + i * 4;
                uint32_t l0, l1;
                uint32_t h0 = pack_hi_lo(v.x, v.y, &l0);
                uint32_t h1 = pack_hi_lo(v.z, v.w, &l1);
                *(uint32_t*)(ah + col * 2) = h0;
                *(uint32_t*)(ah + col * 2 + 4) = h1;
                *(uint32_t*)(al + col * 2) = l0;
                *(uint32_t*)(al + col * 2 + 4) = l1;
            }
        }
        __syncthreads();

        int cur = 0;
        if (br < 11) {
            do_layer(sb, tid, cur, br,      Tb1 + br * 256, true,  true, 0, b0); cur ^= 1;
            do_layer(sb, tid, cur, 11 + br, Tb2 + br * 256, false, true, 0, b0); cur ^= 1;
        }
        do_layer(sb, tid, cur, 22, Eb1, true, true, 0, b0); cur ^= 1;
        do_layer(sb, tid, cur, 23, Eb2, false, false, br, b0);
    }
}

// ---------------- scoring kernel: warp per row ----------------
__global__ void __launch_bounds__(256)
score_kernel(float* __restrict__ out) {
    int lane = threadIdx.x & 31;
    int wid = blockIdx.x * (blockDim.x >> 5) + (threadIdx.x >> 5);
    int nw = gridDim.x * (blockDim.x >> 5);
    for (int row = wid; row < Bq; row += nw) {
        float v[12][8];
#pragma unroll
        for (int s = 0; s < 12; ++s) {
            const float* p = g_z + ((size_t)s * Bq + row) * 256 + lane;
#pragma unroll
            for (int u = 0; u < 8; ++u) v[s][u] = p[u * 32];
        }
        float inrm[12];
#pragma unroll
        for (int s = 0; s < 12; ++s) {
            float d = 0.f;
#pragma unroll
            for (int u = 0; u < 8; ++u) d = fmaf(v[s][u], v[s][u], d);
#pragma unroll
            for (int o = 16; o; o >>= 1) d += __shfl_xor_sync(0xffffffffu, d, o);
            inrm[s] = sqrtf(d);
        }
        float negs[11];
#pragma unroll
        for (int k = 0; k < 11; ++k) negs[k] = 0.f;
#pragma unroll
        for (int l = 0; l < 11; ++l) {
#pragma unroll
            for (int k = l + 1; k < 11; ++k) {
                float d = 0.f;
#pragma unroll
                for (int u = 0; u < 8; ++u) d = fmaf(v[l][u], v[k][u], d);
#pragma unroll
                for (int o = 16; o; o >>= 1) d += __shfl_xor_sync(0xffffffffu, d, o);
                float e = expf(d / fmaxf(inrm[l] * inrm[k], 1e-8f));
                negs[l] += e; negs[k] += e;
            }
        }
        float tot = 0.f;
#pragma unroll
        for (int k = 0; k < 11; ++k) {
            float d = 0.f;
#pragma unroll
            for (int u = 0; u < 8; ++u) d = fmaf(v[11][u], v[k][u], d);
#pragma unroll
            for (int o = 16; o; o >>= 1) d += __shfl_xor_sync(0xffffffffu, d, o);
            float sim = expf(d / fmaxf(inrm[11] * inrm[k], 1e-8f));
            tot += log1pf(negs[k] / sim);
        }
        if (lane == 0) out[row] = tot;
    }
}

// ---------------- launcher ----------------
extern "C" void kernel_launch(void* const* d_in, const int* in_sizes, int n_in,
                              void* d_out, int out_size) {
    const float* x   = (const float*)d_in[0];
    const float* Tw1 = (const float*)d_in[1];
    const float* Tb1 = (const float*)d_in[2];
    const float* Tw2 = (const float*)d_in[3];
    const float* Tb2 = (const float*)d_in[4];
    const float* Ew1 = (const float*)d_in[5];
    const float* Eb1 = (const float*)d_in[6];
    const float* Ew2 = (const float*)d_in[7];
    const float* Eb2 = (const float*)d_in[8];
    float* out = (float*)d_out;

    cudaFuncSetAttribute(mlp_kernel, cudaFuncAttributeMaxDynamicSharedMemorySize, SM_BYTES);

    prep_kernel<<<24, 256>>>(Tw1, Tw2, Ew1, Ew2);
    mlp_kernel<<<Bq / 64, 256, SM_BYTES>>>(x, Tb1, Tb2, Eb1, Eb2);
    score_kernel<<<1024, 256>>>(out);
}